// round 5
// baseline (speedup 1.0000x reference)
#include <cuda_runtime.h>
#include <cuda_bf16.h>

#define IN_DIM 128
#define OUT_DIM 64
#define N_MAX 100000
#define E_MAX 1600000
#define NEG_SLOPE 0.2f

// ---------------- scratch (static device globals: allocation-free) ----------
__device__ float d_h[(size_t)N_MAX * OUT_DIM];     // transformed features
__device__ float d_acc[(size_t)N_MAX * OUT_DIM];   // output accumulator
__device__ float d_as[N_MAX];                      // h @ att_src
__device__ float d_ad[N_MAX];                      // h @ att_dst
__device__ float d_sum[N_MAX];                     // softmax denominator (no max-shift)
__device__ float d_inv[N_MAX];                     // 1 / denominator
__device__ float d_w[E_MAX];                       // per-edge exp weight
__device__ int   d_src[E_MAX];
__device__ int   d_dst[E_MAX];
__device__ int   d_is64;                           // edge_index dtype flag

__device__ __forceinline__ float lrelu(float v) {
    return v > 0.f ? v : NEG_SLOPE * v;
}

// ---------------- K0: detect edge_index element width ------------------------
// If the buffer really is int64, every 64-bit read of the first entries is a
// valid node id in [0, N). If it is int32 data misread as int64, values are
// lo + hi*2^32 with hi a node id (nonzero w.p. ~1-1e-5) -> huge. 64 samples
// make the wrong verdict probability negligible. Reads only 512 bytes.
__global__ void k0_detect(const long long* __restrict__ ei, int N)
{
    int ok64 = 1;
    for (int i = 0; i < 64; i++) {
        long long v = ei[i];
        if (v < 0 || v >= (long long)N) { ok64 = 0; break; }
    }
    d_is64 = ok64;
}

// ---------------- K1: h = x @ W, a_s, a_d, denominator seed (self loop) -----
__global__ __launch_bounds__(512) void k1_gemm(
    const float* __restrict__ x, const float* __restrict__ W,
    const float* __restrict__ att_src, const float* __restrict__ att_dst, int N)
{
    __shared__ float Ws[IN_DIM * OUT_DIM];   // 32 KB
    __shared__ float xs[8][IN_DIM];          // 4 KB
    __shared__ float part[8][2][2];          // [row][half][s/d]

    int t = threadIdx.x;
    for (int i = t; i < IN_DIM * OUT_DIM; i += 512) Ws[i] = W[i];

    int row0 = blockIdx.x * 8;
    for (int i = t; i < 8 * IN_DIM; i += 512) {
        int r = i >> 7, k = i & 127;
        int gr = row0 + r;
        xs[r][k] = (gr < N) ? x[(size_t)gr * IN_DIM + k] : 0.f;
    }
    __syncthreads();

    int r = t >> 6;          // local row 0..7
    int c = t & 63;          // output column 0..63
    int gr = row0 + r;

    float acc = 0.f;
#pragma unroll 16
    for (int k = 0; k < IN_DIM; k++)
        acc = fmaf(xs[r][k], Ws[k * OUT_DIM + c], acc);

    if (gr < N) d_h[(size_t)gr * OUT_DIM + c] = acc;

    float ps = acc * att_src[c];
    float pd = acc * att_dst[c];
#pragma unroll
    for (int o = 16; o; o >>= 1) {
        ps += __shfl_down_sync(0xffffffffu, ps, o);
        pd += __shfl_down_sync(0xffffffffu, pd, o);
    }
    if ((t & 31) == 0) {
        int half = (t >> 5) & 1;
        part[r][half][0] = ps;
        part[r][half][1] = pd;
    }
    __syncthreads();
    if (c == 0 && gr < N) {
        float as = part[r][0][0] + part[r][1][0];
        float ad = part[r][0][1] + part[r][1][1];
        d_as[gr] = as;
        d_ad[gr] = ad;
        // self-loop seeds the softmax denominator (guarantees sum > 0)
        d_sum[gr] = __expf(lrelu(as + ad));
    }
}

// ---------------- K2: decode edges, exp weight, denominator ------------------
__global__ __launch_bounds__(256) void k2_edge(
    const void* __restrict__ ei_raw, int E, int N)
{
    int i = blockIdx.x * blockDim.x + threadIdx.x;
    if (i >= E) return;

    int s, d;
    if (d_is64) {
        const long long* p = (const long long*)ei_raw;
        s = (int)p[i];
        d = (int)p[(size_t)E + i];
    } else {
        const int* p = (const int*)ei_raw;
        s = p[i];
        d = p[(size_t)E + i];
    }
    // defensive clamp: a wrong index becomes wrong data (rel_err), never a trap
    if ((unsigned)s >= (unsigned)N) s = 0;
    if ((unsigned)d >= (unsigned)N) d = 0;

    d_src[i] = s;
    d_dst[i] = d;
    float w = __expf(lrelu(d_as[s] + d_ad[d]));
    d_w[i] = w;
    atomicAdd(&d_sum[d], w);
}

// ---------------- K3: invert denominator ------------------------------------
__global__ __launch_bounds__(256) void k3_inv(int N)
{
    int i = blockIdx.x * blockDim.x + threadIdx.x;
    if (i >= N) return;
    d_inv[i] = 1.f / d_sum[i];
}

// ---------------- K4: acc = bias + alpha_self * h ----------------------------
__global__ __launch_bounds__(256) void k4_acc_init(
    const float* __restrict__ bias, int N)
{
    int i = blockIdx.x * blockDim.x + threadIdx.x;
    if (i >= N * OUT_DIM) return;
    int node = i >> 6, c = i & 63;
    float a_self = __expf(lrelu(d_as[node] + d_ad[node])) * d_inv[node];
    d_acc[i] = bias[c] + a_self * d_h[i];
}

// ---------------- K5: weighted scatter-add into device accumulator -----------
// 64 lanes per edge; each lane does ONE scalar float atomicAdd into d_acc.
__global__ __launch_bounds__(256) void k5_aggregate(int E)
{
    int g = blockIdx.x * blockDim.x + threadIdx.x;
    int edge = g >> 6;
    int l = g & 63;
    if (edge >= E) return;
    int s = d_src[edge];
    int d = d_dst[edge];
    float alpha = d_w[edge] * d_inv[d];
    float v = d_h[s * OUT_DIM + l];
    atomicAdd(&d_acc[d * OUT_DIM + l], v * alpha);
}

// ---------------- K6: plain vectorized copy accumulator -> out ---------------
__global__ __launch_bounds__(256) void k6_copy(float4* __restrict__ out, int n4)
{
    int i = blockIdx.x * blockDim.x + threadIdx.x;
    if (i >= n4) return;
    out[i] = reinterpret_cast<const float4*>(d_acc)[i];
}

// ---------------- launch ------------------------------------------------------
extern "C" void kernel_launch(void* const* d_in, const int* in_sizes, int n_in,
                              void* d_out, int out_size)
{
    const float* x    = (const float*)d_in[0];
    const void*  ei   = d_in[1];
    const float* W    = (const float*)d_in[2];
    const float* asrc = (const float*)d_in[3];
    const float* adst = (const float*)d_in[4];
    const float* bias = (const float*)d_in[5];
    float*       out  = (float*)d_out;

    int N = in_sizes[0] / IN_DIM;
    int E = in_sizes[1] / 2;

    k0_detect<<<1, 1>>>((const long long*)ei, N);
    k1_gemm<<<(N + 7) / 8, 512>>>(x, W, asrc, adst, N);
    k2_edge<<<(E + 255) / 256, 256>>>(ei, E, N);
    k3_inv<<<(N + 255) / 256, 256>>>(N);
    k4_acc_init<<<(N * OUT_DIM + 255) / 256, 256>>>(bias, N);
    {
        long long total = (long long)E * OUT_DIM;
        int blocks = (int)((total + 255) / 256);
        k5_aggregate<<<blocks, 256>>>(E);
    }
    {
        int n4 = N * OUT_DIM / 4;
        k6_copy<<<(n4 + 255) / 256, 256>>>((float4*)out, n4);
    }
}

// round 6
// speedup vs baseline: 1.1949x; 1.1949x over previous
#include <cuda_runtime.h>
#include <cuda_bf16.h>

#define IN_DIM 128
#define OUT_DIM 64
#define N_MAX 100000
#define E_MAX 1600000
#define NEG_SLOPE 0.2f

// ---------------- scratch (static device globals: allocation-free) ----------
__device__ float d_h[(size_t)N_MAX * OUT_DIM];   // transformed features
__device__ float d_as[N_MAX];                    // h @ att_src
__device__ float d_ad[N_MAX];                    // h @ att_dst
__device__ float d_sum[N_MAX];                   // softmax denominator (no max-shift)
__device__ float d_w[E_MAX];                     // per-edge exp weight (edge order)
__device__ int   d_src[E_MAX];                   // decoded src (edge order)
__device__ int   d_dstv[E_MAX];                  // decoded dst (edge order)
__device__ int   d_deg[N_MAX];                   // in-degree histogram
__device__ int   d_start[N_MAX + 1];             // CSR row offsets (by dst)
__device__ int   d_cursor[N_MAX];                // placement cursors
__device__ int   d_ssrc[E_MAX];                  // bucketed src
__device__ float d_sw[E_MAX];                    // bucketed weight
__device__ int   d_is64;                         // edge_index dtype flag

__device__ __forceinline__ float lrelu(float v) {
    return v > 0.f ? v : NEG_SLOPE * v;
}

// ---------------- K0: detect edge_index element width ------------------------
__global__ void k0_detect(const long long* __restrict__ ei, int N)
{
    int ok64 = 1;
    for (int i = 0; i < 64; i++) {
        long long v = ei[i];
        if (v < 0 || v >= (long long)N) { ok64 = 0; break; }
    }
    d_is64 = ok64;
}

// ---------------- K1: h = x @ W (4 cols/thread), a_s, a_d, seeds -------------
__global__ __launch_bounds__(256) void k1_gemm(
    const float* __restrict__ x, const float* __restrict__ W,
    const float* __restrict__ att_src, const float* __restrict__ att_dst, int N)
{
    __shared__ float Ws[IN_DIM * OUT_DIM];        // 32 KB, row-major [k][64]
    __shared__ float xs[16][IN_DIM + 1];          // padded: rows hit distinct banks

    int t = threadIdx.x;
    for (int i = t; i < IN_DIM * OUT_DIM; i += 256) Ws[i] = W[i];

    int row0 = blockIdx.x * 16;
    for (int i = t; i < 16 * IN_DIM; i += 256) {
        int r = i >> 7, k = i & 127;
        int gr = row0 + r;
        xs[r][k] = (gr < N) ? x[(size_t)gr * IN_DIM + k] : 0.f;
    }
    __syncthreads();

    int r  = t >> 4;          // local row 0..15
    int cg = t & 15;          // col group (4 cols each)
    int gr = row0 + r;

    const float4* W4 = reinterpret_cast<const float4*>(Ws);
    float4 acc = make_float4(0.f, 0.f, 0.f, 0.f);
#pragma unroll 8
    for (int k = 0; k < IN_DIM; k++) {
        float xv = xs[r][k];
        float4 w = W4[k * 16 + cg];
        acc.x = fmaf(xv, w.x, acc.x);
        acc.y = fmaf(xv, w.y, acc.y);
        acc.z = fmaf(xv, w.z, acc.z);
        acc.w = fmaf(xv, w.w, acc.w);
    }
    if (gr < N)
        reinterpret_cast<float4*>(d_h)[(size_t)gr * 16 + cg] = acc;

    float4 As4 = reinterpret_cast<const float4*>(att_src)[cg];
    float4 Ad4 = reinterpret_cast<const float4*>(att_dst)[cg];
    float ps = acc.x * As4.x + acc.y * As4.y + acc.z * As4.z + acc.w * As4.w;
    float pd = acc.x * Ad4.x + acc.y * Ad4.y + acc.z * Ad4.z + acc.w * Ad4.w;
#pragma unroll
    for (int o = 8; o; o >>= 1) {
        ps += __shfl_down_sync(0xffffffffu, ps, o);
        pd += __shfl_down_sync(0xffffffffu, pd, o);
    }
    if (cg == 0 && gr < N) {
        d_as[gr] = ps;
        d_ad[gr] = pd;
        d_sum[gr] = __expf(lrelu(ps + pd));   // self-loop seeds denominator
        d_deg[gr] = 0;                        // zero histogram for this replay
    }
}

// ---------------- K2a: decode edges, exp weight, denominator, degree --------
__global__ __launch_bounds__(256) void k2a_edge(
    const void* __restrict__ ei_raw, int E, int N)
{
    int i = blockIdx.x * blockDim.x + threadIdx.x;
    if (i >= E) return;

    int s, d;
    if (d_is64) {
        const long long* p = (const long long*)ei_raw;
        s = (int)p[i];
        d = (int)p[(size_t)E + i];
    } else {
        const int* p = (const int*)ei_raw;
        s = p[i];
        d = p[(size_t)E + i];
    }
    if ((unsigned)s >= (unsigned)N) s = 0;   // trap-proofing
    if ((unsigned)d >= (unsigned)N) d = 0;

    d_src[i]  = s;
    d_dstv[i] = d;
    float w = __expf(lrelu(d_as[s] + d_ad[d]));
    d_w[i] = w;
    atomicAdd(&d_sum[d], w);
    atomicAdd(&d_deg[d], 1);
}

// ---------------- K2b: exclusive scan of degrees (1 block, deterministic) ---
__global__ __launch_bounds__(1024) void k2b_scan(int N)
{
    __shared__ int part[1024];
    int t = threadIdx.x;
    int chunk = (N + 1023) / 1024;
    int b = t * chunk;
    int e = min(b + chunk, N);

    int s = 0;
    for (int i = b; i < e; i++) s += d_deg[i];
    part[t] = s;
    __syncthreads();
#pragma unroll
    for (int off = 1; off < 1024; off <<= 1) {
        int v = (t >= off) ? part[t - off] : 0;
        __syncthreads();
        part[t] += v;
        __syncthreads();
    }
    int run = (t > 0) ? part[t - 1] : 0;
    for (int i = b; i < e; i++) {
        d_start[i]  = run;
        d_cursor[i] = run;
        run += d_deg[i];
    }
    if (e == N) d_start[N] = run;   // all qualifying threads write the total
}

// ---------------- K2c: place (src, w) records into dst buckets ---------------
__global__ __launch_bounds__(256) void k2c_place(int E)
{
    int i = blockIdx.x * blockDim.x + threadIdx.x;
    if (i >= E) return;
    int d = d_dstv[i];
    int p = atomicAdd(&d_cursor[d], 1);
    d_ssrc[p] = d_src[i];
    d_sw[p]   = d_w[i];
}

// ---------------- K5: per-node gather-aggregate (one warp per node) ----------
// Registers accumulate 2 columns per lane; edge records are staged 32 at a
// time into registers and shfl-broadcast. No float atomics anywhere.
__global__ __launch_bounds__(256) void k5_gather(
    float2* __restrict__ out, const float* __restrict__ bias, int N)
{
    int t = threadIdx.x;
    int warp = t >> 5, lane = t & 31;
    int n = blockIdx.x * 8 + warp;
    if (n >= N) return;

    const float2* h2 = reinterpret_cast<const float2*>(d_h);

    float wself = __expf(lrelu(d_as[n] + d_ad[n]));
    float2 hv = h2[(size_t)n * 32 + lane];
    float accx = wself * hv.x;
    float accy = wself * hv.y;

    int beg = d_start[n], end = d_start[n + 1];
    for (int e0 = beg; e0 < end; e0 += 32) {
        int k = min(32, end - e0);
        int   sreg = 0;
        float wreg = 0.f;
        if (lane < k) {
            sreg = d_ssrc[e0 + lane];
            wreg = d_sw[e0 + lane];
        }
        for (int j = 0; j < k; j++) {
            int   sj = __shfl_sync(0xffffffffu, sreg, j);
            float wj = __shfl_sync(0xffffffffu, wreg, j);
            float2 v = h2[(size_t)sj * 32 + lane];
            accx = fmaf(wj, v.x, accx);
            accy = fmaf(wj, v.y, accy);
        }
    }
    float inv = 1.f / d_sum[n];
    float2 b = reinterpret_cast<const float2*>(bias)[lane];
    out[(size_t)n * 32 + lane] = make_float2(accx * inv + b.x, accy * inv + b.y);
}

// ---------------- launch ------------------------------------------------------
extern "C" void kernel_launch(void* const* d_in, const int* in_sizes, int n_in,
                              void* d_out, int out_size)
{
    const float* x    = (const float*)d_in[0];
    const void*  ei   = d_in[1];
    const float* W    = (const float*)d_in[2];
    const float* asrc = (const float*)d_in[3];
    const float* adst = (const float*)d_in[4];
    const float* bias = (const float*)d_in[5];
    float*       out  = (float*)d_out;

    int N = in_sizes[0] / IN_DIM;
    int E = in_sizes[1] / 2;

    k0_detect<<<1, 1>>>((const long long*)ei, N);
    k1_gemm<<<(N + 15) / 16, 256>>>(x, W, asrc, adst, N);
    k2a_edge<<<(E + 255) / 256, 256>>>(ei, E, N);
    k2b_scan<<<1, 1024>>>(N);
    k2c_place<<<(E + 255) / 256, 256>>>(E);
    k5_gather<<<(N + 7) / 8, 256>>>((float2*)out, bias, N);
}

// round 7
// speedup vs baseline: 1.9372x; 1.6212x over previous
#include <cuda_runtime.h>
#include <cuda_bf16.h>

#define IN_DIM 128
#define OUT_DIM 64
#define N_MAX 100000
#define E_MAX 1600000
#define NEG_SLOPE 0.2f

// ---------------- scratch (static device globals: allocation-free) ----------
__device__ float d_h[(size_t)N_MAX * OUT_DIM];   // transformed features
__device__ float d_as[N_MAX];                    // h @ att_src
__device__ float d_ad[N_MAX];                    // h @ att_dst
__device__ float d_sum[N_MAX];                   // softmax denominator (no max-shift)
__device__ int   d_deg[N_MAX];                   // in-degree histogram
__device__ int   d_excl[N_MAX];                  // tile-local exclusive prefix
__device__ int   d_bsum[128];                    // per-tile totals
__device__ int   d_boff[128];                    // per-tile exclusive offsets
__device__ int   d_start[N_MAX + 1];             // CSR row offsets (by dst)
__device__ int   d_cursor[N_MAX];                // placement cursors
__device__ int   d_ssrc[E_MAX];                  // bucketed src
__device__ float d_sw[E_MAX];                    // bucketed weight
__device__ int   d_is64;                         // edge_index dtype flag

__device__ __forceinline__ float lrelu(float v) {
    return v > 0.f ? v : NEG_SLOPE * v;
}

// ---------------- K0: detect edge_index element width ------------------------
__global__ void k0_detect(const long long* __restrict__ ei, int N)
{
    int ok64 = 1;
    for (int i = 0; i < 64; i++) {
        long long v = ei[i];
        if (v < 0 || v >= (long long)N) { ok64 = 0; break; }
    }
    d_is64 = ok64;
}

// ---------------- K1: h = x @ W (4 cols/thread), a_s, a_d, seeds -------------
__global__ __launch_bounds__(256) void k1_gemm(
    const float* __restrict__ x, const float* __restrict__ W,
    const float* __restrict__ att_src, const float* __restrict__ att_dst, int N)
{
    __shared__ float Ws[IN_DIM * OUT_DIM];        // 32 KB, row-major [k][64]
    __shared__ float xs[16][IN_DIM + 1];

    int t = threadIdx.x;
    for (int i = t; i < IN_DIM * OUT_DIM; i += 256) Ws[i] = W[i];

    int row0 = blockIdx.x * 16;
    for (int i = t; i < 16 * IN_DIM; i += 256) {
        int r = i >> 7, k = i & 127;
        int gr = row0 + r;
        xs[r][k] = (gr < N) ? x[(size_t)gr * IN_DIM + k] : 0.f;
    }
    __syncthreads();

    int r  = t >> 4;          // local row 0..15
    int cg = t & 15;          // col group (4 cols each)
    int gr = row0 + r;

    const float4* W4 = reinterpret_cast<const float4*>(Ws);
    float4 acc = make_float4(0.f, 0.f, 0.f, 0.f);
#pragma unroll 8
    for (int k = 0; k < IN_DIM; k++) {
        float xv = xs[r][k];
        float4 w = W4[k * 16 + cg];
        acc.x = fmaf(xv, w.x, acc.x);
        acc.y = fmaf(xv, w.y, acc.y);
        acc.z = fmaf(xv, w.z, acc.z);
        acc.w = fmaf(xv, w.w, acc.w);
    }
    if (gr < N)
        reinterpret_cast<float4*>(d_h)[(size_t)gr * 16 + cg] = acc;

    float4 As4 = reinterpret_cast<const float4*>(att_src)[cg];
    float4 Ad4 = reinterpret_cast<const float4*>(att_dst)[cg];
    float ps = acc.x * As4.x + acc.y * As4.y + acc.z * As4.z + acc.w * As4.w;
    float pd = acc.x * Ad4.x + acc.y * Ad4.y + acc.z * Ad4.z + acc.w * Ad4.w;
#pragma unroll
    for (int o = 8; o; o >>= 1) {
        ps += __shfl_down_sync(0xffffffffu, ps, o);
        pd += __shfl_down_sync(0xffffffffu, pd, o);
    }
    if (cg == 0 && gr < N) {
        d_as[gr] = ps;
        d_ad[gr] = pd;
        d_sum[gr] = __expf(lrelu(ps + pd));   // self-loop seeds denominator
        d_deg[gr] = 0;                        // zero histogram for this replay
    }
}

// ---------------- K2a: dst-degree histogram (reads dst half only) ------------
__global__ __launch_bounds__(256) void k2a_hist(
    const void* __restrict__ ei_raw, int E, int N)
{
    int i = blockIdx.x * blockDim.x + threadIdx.x;
    if (i >= E) return;
    int d;
    if (d_is64) {
        d = (int)((const long long*)ei_raw)[(size_t)E + i];
    } else {
        d = ((const int*)ei_raw)[(size_t)E + i];
    }
    if ((unsigned)d >= (unsigned)N) d = 0;
    atomicAdd(&d_deg[d], 1);
}

// ---------------- kS1/kS2/kS3: parallel 3-stage exclusive scan ---------------
__global__ __launch_bounds__(1024) void kS1_tile_scan(int N)
{
    __shared__ int sh[1024];
    int t = threadIdx.x;
    int gi = blockIdx.x * 1024 + t;
    int v = (gi < N) ? d_deg[gi] : 0;
    sh[t] = v;
    __syncthreads();
#pragma unroll
    for (int off = 1; off < 1024; off <<= 1) {
        int u = (t >= off) ? sh[t - off] : 0;
        __syncthreads();
        sh[t] += u;
        __syncthreads();
    }
    if (gi < N) d_excl[gi] = sh[t] - v;
    if (t == 1023) d_bsum[blockIdx.x] = sh[t];
}

__global__ __launch_bounds__(128) void kS2_block_scan(int nTiles)
{
    __shared__ int sh[128];
    int t = threadIdx.x;
    int v = (t < nTiles) ? d_bsum[t] : 0;
    sh[t] = v;
    __syncthreads();
#pragma unroll
    for (int off = 1; off < 128; off <<= 1) {
        int u = (t >= off) ? sh[t - off] : 0;
        __syncthreads();
        sh[t] += u;
        __syncthreads();
    }
    if (t < nTiles) d_boff[t] = sh[t] - v;
}

__global__ __launch_bounds__(256) void kS3_finalize(int N, int E)
{
    int i = blockIdx.x * blockDim.x + threadIdx.x;
    if (i < N) {
        int s = d_excl[i] + d_boff[i >> 10];
        d_start[i]  = s;
        d_cursor[i] = s;
    }
    if (i == 0) d_start[N] = E;   // clamp drops no edges: total is exactly E
}

// ---------------- K2c: decode + weight + denominator + place -----------------
__global__ __launch_bounds__(256) void k2c_place(
    const void* __restrict__ ei_raw, int E, int N)
{
    int i = blockIdx.x * blockDim.x + threadIdx.x;
    if (i >= E) return;
    int s, d;
    if (d_is64) {
        const long long* p = (const long long*)ei_raw;
        s = (int)p[i];
        d = (int)p[(size_t)E + i];
    } else {
        const int* p = (const int*)ei_raw;
        s = p[i];
        d = p[(size_t)E + i];
    }
    if ((unsigned)s >= (unsigned)N) s = 0;
    if ((unsigned)d >= (unsigned)N) d = 0;

    float w = __expf(lrelu(d_as[s] + d_ad[d]));
    atomicAdd(&d_sum[d], w);
    int p = atomicAdd(&d_cursor[d], 1);
    d_ssrc[p] = s;
    d_sw[p]   = w;
}

// ---------------- K5: per-node gather-aggregate (one warp per node) ----------
__global__ __launch_bounds__(256) void k5_gather(
    float2* __restrict__ out, const float* __restrict__ bias, int N)
{
    int t = threadIdx.x;
    int warp = t >> 5, lane = t & 31;
    int n = blockIdx.x * 8 + warp;
    if (n >= N) return;

    const float2* h2 = reinterpret_cast<const float2*>(d_h);

    float wself = __expf(lrelu(d_as[n] + d_ad[n]));
    float2 hv = h2[(size_t)n * 32 + lane];
    float accx = wself * hv.x;
    float accy = wself * hv.y;

    int beg = d_start[n], end = d_start[n + 1];
    for (int e0 = beg; e0 < end; e0 += 32) {
        int k = min(32, end - e0);
        int   sreg = 0;
        float wreg = 0.f;
        if (lane < k) {
            sreg = d_ssrc[e0 + lane];
            wreg = d_sw[e0 + lane];
        }
        for (int j = 0; j < k; j++) {
            int   sj = __shfl_sync(0xffffffffu, sreg, j);
            float wj = __shfl_sync(0xffffffffu, wreg, j);
            float2 v = h2[(size_t)sj * 32 + lane];
            accx = fmaf(wj, v.x, accx);
            accy = fmaf(wj, v.y, accy);
        }
    }
    float inv = 1.f / d_sum[n];
    float2 b = reinterpret_cast<const float2*>(bias)[lane];
    out[(size_t)n * 32 + lane] = make_float2(accx * inv + b.x, accy * inv + b.y);
}

// ---------------- launch ------------------------------------------------------
extern "C" void kernel_launch(void* const* d_in, const int* in_sizes, int n_in,
                              void* d_out, int out_size)
{
    const float* x    = (const float*)d_in[0];
    const void*  ei   = d_in[1];
    const float* W    = (const float*)d_in[2];
    const float* asrc = (const float*)d_in[3];
    const float* adst = (const float*)d_in[4];
    const float* bias = (const float*)d_in[5];
    float*       out  = (float*)d_out;

    int N = in_sizes[0] / IN_DIM;
    int E = in_sizes[1] / 2;
    int nTiles = (N + 1023) / 1024;    // <= 128 for N <= 100k

    k0_detect<<<1, 1>>>((const long long*)ei, N);
    k1_gemm<<<(N + 15) / 16, 256>>>(x, W, asrc, adst, N);
    k2a_hist<<<(E + 255) / 256, 256>>>(ei, E, N);
    kS1_tile_scan<<<nTiles, 1024>>>(N);
    kS2_block_scan<<<1, 128>>>(nTiles);
    kS3_finalize<<<(N + 255) / 256, 256>>>(N, E);
    k2c_place<<<(E + 255) / 256, 256>>>(ei, E, N);
    k5_gather<<<(N + 7) / 8, 256>>>((float2*)out, bias, N);
}

// round 8
// speedup vs baseline: 2.0506x; 1.0586x over previous
#include <cuda_runtime.h>
#include <cuda_bf16.h>

#define IN_DIM 128
#define OUT_DIM 64
#define N_MAX 100000
#define E_MAX 1600000
#define NEG_SLOPE 0.2f

// ---------------- scratch (static device globals: allocation-free) ----------
__device__ float d_h[(size_t)N_MAX * OUT_DIM];   // transformed features
__device__ float d_as[N_MAX];                    // h @ att_src
__device__ float d_ad[N_MAX];                    // h @ att_dst
__device__ int   d_deg[N_MAX];                   // in-degree histogram
__device__ int   d_excl[N_MAX];                  // tile-local exclusive prefix
__device__ int   d_bsum[128];                    // per-tile totals
__device__ int   d_boff[128];                    // per-tile exclusive offsets
__device__ int   d_start[N_MAX + 1];             // CSR row offsets (by dst)
__device__ int   d_cursor[N_MAX];                // placement cursors
__device__ int2  d_rec[E_MAX];                   // bucketed (src, w-as-bits)
__device__ int   d_is64;                         // edge_index dtype flag

__device__ __forceinline__ float lrelu(float v) {
    return v > 0.f ? v : NEG_SLOPE * v;
}

// ---------------- K0: detect edge_index element width ------------------------
__global__ void k0_detect(const long long* __restrict__ ei, int N)
{
    int ok64 = 1;
    for (int i = 0; i < 64; i++) {
        long long v = ei[i];
        if (v < 0 || v >= (long long)N) { ok64 = 0; break; }
    }
    d_is64 = ok64;
}

// ---------------- K1: h = x @ W (4 cols/thread), a_s, a_d --------------------
__global__ __launch_bounds__(256) void k1_gemm(
    const float* __restrict__ x, const float* __restrict__ W,
    const float* __restrict__ att_src, const float* __restrict__ att_dst, int N)
{
    __shared__ float Ws[IN_DIM * OUT_DIM];        // 32 KB, row-major [k][64]
    __shared__ float xs[16][IN_DIM + 1];

    int t = threadIdx.x;
    for (int i = t; i < IN_DIM * OUT_DIM; i += 256) Ws[i] = W[i];

    int row0 = blockIdx.x * 16;
    for (int i = t; i < 16 * IN_DIM; i += 256) {
        int r = i >> 7, k = i & 127;
        int gr = row0 + r;
        xs[r][k] = (gr < N) ? x[(size_t)gr * IN_DIM + k] : 0.f;
    }
    __syncthreads();

    int r  = t >> 4;          // local row 0..15
    int cg = t & 15;          // col group (4 cols each)
    int gr = row0 + r;

    const float4* W4 = reinterpret_cast<const float4*>(Ws);
    float4 acc = make_float4(0.f, 0.f, 0.f, 0.f);
#pragma unroll 8
    for (int k = 0; k < IN_DIM; k++) {
        float xv = xs[r][k];
        float4 w = W4[k * 16 + cg];
        acc.x = fmaf(xv, w.x, acc.x);
        acc.y = fmaf(xv, w.y, acc.y);
        acc.z = fmaf(xv, w.z, acc.z);
        acc.w = fmaf(xv, w.w, acc.w);
    }
    if (gr < N)
        reinterpret_cast<float4*>(d_h)[(size_t)gr * 16 + cg] = acc;

    float4 As4 = reinterpret_cast<const float4*>(att_src)[cg];
    float4 Ad4 = reinterpret_cast<const float4*>(att_dst)[cg];
    float ps = acc.x * As4.x + acc.y * As4.y + acc.z * As4.z + acc.w * As4.w;
    float pd = acc.x * Ad4.x + acc.y * Ad4.y + acc.z * Ad4.z + acc.w * Ad4.w;
#pragma unroll
    for (int o = 8; o; o >>= 1) {
        ps += __shfl_down_sync(0xffffffffu, ps, o);
        pd += __shfl_down_sync(0xffffffffu, pd, o);
    }
    if (cg == 0 && gr < N) {
        d_as[gr] = ps;
        d_ad[gr] = pd;
        d_deg[gr] = 0;                        // zero histogram for this replay
    }
}

// ---------------- K2a: dst-degree histogram (reads dst half only) ------------
__global__ __launch_bounds__(256) void k2a_hist(
    const void* __restrict__ ei_raw, int E, int N)
{
    int i = blockIdx.x * blockDim.x + threadIdx.x;
    if (i >= E) return;
    int d;
    if (d_is64) {
        d = (int)((const long long*)ei_raw)[(size_t)E + i];
    } else {
        d = ((const int*)ei_raw)[(size_t)E + i];
    }
    if ((unsigned)d >= (unsigned)N) d = 0;
    atomicAdd(&d_deg[d], 1);
}

// ---------------- kS1/kS2/kS3: parallel 3-stage exclusive scan ---------------
__global__ __launch_bounds__(1024) void kS1_tile_scan(int N)
{
    __shared__ int sh[1024];
    int t = threadIdx.x;
    int gi = blockIdx.x * 1024 + t;
    int v = (gi < N) ? d_deg[gi] : 0;
    sh[t] = v;
    __syncthreads();
#pragma unroll
    for (int off = 1; off < 1024; off <<= 1) {
        int u = (t >= off) ? sh[t - off] : 0;
        __syncthreads();
        sh[t] += u;
        __syncthreads();
    }
    if (gi < N) d_excl[gi] = sh[t] - v;
    if (t == 1023) d_bsum[blockIdx.x] = sh[t];
}

__global__ __launch_bounds__(128) void kS2_block_scan(int nTiles)
{
    __shared__ int sh[128];
    int t = threadIdx.x;
    int v = (t < nTiles) ? d_bsum[t] : 0;
    sh[t] = v;
    __syncthreads();
#pragma unroll
    for (int off = 1; off < 128; off <<= 1) {
        int u = (t >= off) ? sh[t - off] : 0;
        __syncthreads();
        sh[t] += u;
        __syncthreads();
    }
    if (t < nTiles) d_boff[t] = sh[t] - v;
}

__global__ __launch_bounds__(256) void kS3_finalize(int N, int E)
{
    int i = blockIdx.x * blockDim.x + threadIdx.x;
    if (i < N) {
        int s = d_excl[i] + d_boff[i >> 10];
        d_start[i]  = s;
        d_cursor[i] = s;
    }
    if (i == 0) d_start[N] = E;   // clamp drops no edges: total is exactly E
}

// ---------------- K2c: decode + weight + place (single 8B record store) ------
__global__ __launch_bounds__(256) void k2c_place(
    const void* __restrict__ ei_raw, int E, int N)
{
    int i = blockIdx.x * blockDim.x + threadIdx.x;
    if (i >= E) return;
    int s, d;
    if (d_is64) {
        const long long* p = (const long long*)ei_raw;
        s = (int)p[i];
        d = (int)p[(size_t)E + i];
    } else {
        const int* p = (const int*)ei_raw;
        s = p[i];
        d = p[(size_t)E + i];
    }
    if ((unsigned)s >= (unsigned)N) s = 0;
    if ((unsigned)d >= (unsigned)N) d = 0;

    float w = __expf(lrelu(d_as[s] + d_ad[d]));
    int p = atomicAdd(&d_cursor[d], 1);
    d_rec[p] = make_int2(s, __float_as_int(w));
}

// ---------------- K5: per-node gather-aggregate (one warp per node) ----------
// Denominator computed in-register from the bucketed weights (no atomics).
__global__ __launch_bounds__(256) void k5_gather(
    float2* __restrict__ out, const float* __restrict__ bias, int N)
{
    int t = threadIdx.x;
    int warp = t >> 5, lane = t & 31;
    int n = blockIdx.x * 8 + warp;
    if (n >= N) return;

    const float2* h2 = reinterpret_cast<const float2*>(d_h);

    float wself = __expf(lrelu(d_as[n] + d_ad[n]));
    float2 hv = h2[(size_t)n * 32 + lane];
    float accx = wself * hv.x;
    float accy = wself * hv.y;
    float wsum = wself;

    int beg = d_start[n], end = d_start[n + 1];
    for (int e0 = beg; e0 < end; e0 += 32) {
        int k = min(32, end - e0);
        int2 rec = make_int2(0, 0);
        if (lane < k) rec = d_rec[e0 + lane];
        for (int j = 0; j < k; j++) {
            int   sj = __shfl_sync(0xffffffffu, rec.x, j);
            float wj = __int_as_float(__shfl_sync(0xffffffffu, rec.y, j));
            float2 v = h2[(size_t)sj * 32 + lane];
            accx = fmaf(wj, v.x, accx);
            accy = fmaf(wj, v.y, accy);
            wsum += wj;
        }
    }
    float inv = 1.f / wsum;
    float2 b = reinterpret_cast<const float2*>(bias)[lane];
    out[(size_t)n * 32 + lane] = make_float2(accx * inv + b.x, accy * inv + b.y);
}

// ---------------- launch ------------------------------------------------------
extern "C" void kernel_launch(void* const* d_in, const int* in_sizes, int n_in,
                              void* d_out, int out_size)
{
    const float* x    = (const float*)d_in[0];
    const void*  ei   = d_in[1];
    const float* W    = (const float*)d_in[2];
    const float* asrc = (const float*)d_in[3];
    const float* adst = (const float*)d_in[4];
    const float* bias = (const float*)d_in[5];
    float*       out  = (float*)d_out;

    int N = in_sizes[0] / IN_DIM;
    int E = in_sizes[1] / 2;
    int nTiles = (N + 1023) / 1024;    // <= 128 for N <= 100k

    k0_detect<<<1, 1>>>((const long long*)ei, N);
    k1_gemm<<<(N + 15) / 16, 256>>>(x, W, asrc, adst, N);
    k2a_hist<<<(E + 255) / 256, 256>>>(ei, E, N);
    kS1_tile_scan<<<nTiles, 1024>>>(N);
    kS2_block_scan<<<1, 128>>>(nTiles);
    kS3_finalize<<<(N + 255) / 256, 256>>>(N, E);
    k2c_place<<<(E + 255) / 256, 256>>>(ei, E, N);
    k5_gather<<<(N + 7) / 8, 256>>>((float2*)out, bias, N);
}

// round 9
// speedup vs baseline: 2.3589x; 1.1503x over previous
#include <cuda_runtime.h>
#include <cuda_bf16.h>

#define IN_DIM 128
#define OUT_DIM 64
#define N_MAX 100000
#define E_MAX 1600000
#define NEG_SLOPE 0.2f

// ---------------- scratch (static device globals: allocation-free) ----------
__device__ float d_h[(size_t)N_MAX * OUT_DIM];   // transformed features
__device__ float d_as[N_MAX];                    // h @ att_src
__device__ float d_ad[N_MAX];                    // h @ att_dst
__device__ int   d_deg[N_MAX];                   // in-degree histogram
__device__ int   d_excl[N_MAX];                  // tile-local exclusive prefix
__device__ int   d_bsum[128];                    // per-tile totals
__device__ int   d_boff[128];                    // per-tile exclusive offsets
__device__ int   d_start[N_MAX + 1];             // CSR row offsets (by dst)
__device__ int   d_cursor[N_MAX];                // placement cursors
__device__ int2  d_rec[E_MAX];                   // bucketed (src, w-as-bits)
__device__ int   d_is64;                         // edge_index dtype flag

__device__ __forceinline__ float lrelu(float v) {
    return v > 0.f ? v : NEG_SLOPE * v;
}

// ---------------- K0: detect edge_index element width ------------------------
__global__ void k0_detect(const long long* __restrict__ ei, int N)
{
    int ok64 = 1;
    for (int i = 0; i < 64; i++) {
        long long v = ei[i];
        if (v < 0 || v >= (long long)N) { ok64 = 0; break; }
    }
    d_is64 = ok64;
}

// ---------------- K1: h = x @ W (2 rows x 4 cols per thread) -----------------
__global__ __launch_bounds__(256) void k1_gemm(
    const float* __restrict__ x, const float* __restrict__ W,
    const float* __restrict__ att_src, const float* __restrict__ att_dst, int N)
{
    __shared__ float Ws[IN_DIM * OUT_DIM];        // 32 KB, row-major [k][64]
    __shared__ float xs[32][IN_DIM + 1];          // 16.5 KB

    int t = threadIdx.x;
    for (int i = t; i < IN_DIM * OUT_DIM; i += 256) Ws[i] = W[i];

    int row0 = blockIdx.x * 32;
    for (int i = t; i < 32 * IN_DIM; i += 256) {
        int r = i >> 7, k = i & 127;
        int gr = row0 + r;
        xs[r][k] = (gr < N) ? x[(size_t)gr * IN_DIM + k] : 0.f;
    }
    __syncthreads();

    int r  = t >> 4;          // local row pair base: rows r and r+16
    int cg = t & 15;          // col group (4 cols each)
    int gr0 = row0 + r;
    int gr1 = row0 + r + 16;

    const float4* W4 = reinterpret_cast<const float4*>(Ws);
    float4 a0 = make_float4(0.f, 0.f, 0.f, 0.f);
    float4 a1 = make_float4(0.f, 0.f, 0.f, 0.f);
#pragma unroll 8
    for (int k = 0; k < IN_DIM; k++) {
        float4 w = W4[k * 16 + cg];
        float x0 = xs[r][k];
        float x1 = xs[r + 16][k];
        a0.x = fmaf(x0, w.x, a0.x); a0.y = fmaf(x0, w.y, a0.y);
        a0.z = fmaf(x0, w.z, a0.z); a0.w = fmaf(x0, w.w, a0.w);
        a1.x = fmaf(x1, w.x, a1.x); a1.y = fmaf(x1, w.y, a1.y);
        a1.z = fmaf(x1, w.z, a1.z); a1.w = fmaf(x1, w.w, a1.w);
    }
    if (gr0 < N) reinterpret_cast<float4*>(d_h)[(size_t)gr0 * 16 + cg] = a0;
    if (gr1 < N) reinterpret_cast<float4*>(d_h)[(size_t)gr1 * 16 + cg] = a1;

    float4 As4 = reinterpret_cast<const float4*>(att_src)[cg];
    float4 Ad4 = reinterpret_cast<const float4*>(att_dst)[cg];
    float ps0 = a0.x * As4.x + a0.y * As4.y + a0.z * As4.z + a0.w * As4.w;
    float pd0 = a0.x * Ad4.x + a0.y * Ad4.y + a0.z * Ad4.z + a0.w * Ad4.w;
    float ps1 = a1.x * As4.x + a1.y * As4.y + a1.z * As4.z + a1.w * As4.w;
    float pd1 = a1.x * Ad4.x + a1.y * Ad4.y + a1.z * Ad4.z + a1.w * Ad4.w;
#pragma unroll
    for (int o = 8; o; o >>= 1) {
        ps0 += __shfl_down_sync(0xffffffffu, ps0, o);
        pd0 += __shfl_down_sync(0xffffffffu, pd0, o);
        ps1 += __shfl_down_sync(0xffffffffu, ps1, o);
        pd1 += __shfl_down_sync(0xffffffffu, pd1, o);
    }
    if (cg == 0) {
        if (gr0 < N) { d_as[gr0] = ps0; d_ad[gr0] = pd0; d_deg[gr0] = 0; }
        if (gr1 < N) { d_as[gr1] = ps1; d_ad[gr1] = pd1; d_deg[gr1] = 0; }
    }
}

// ---------------- K2a: dst-degree histogram (reads dst half only) ------------
__global__ __launch_bounds__(256) void k2a_hist(
    const void* __restrict__ ei_raw, int E, int N)
{
    int i = blockIdx.x * blockDim.x + threadIdx.x;
    if (i >= E) return;
    int d;
    if (d_is64) {
        d = (int)((const long long*)ei_raw)[(size_t)E + i];
    } else {
        d = ((const int*)ei_raw)[(size_t)E + i];
    }
    if ((unsigned)d >= (unsigned)N) d = 0;
    atomicAdd(&d_deg[d], 1);
}

// ---------------- kS1/kS2/kS3: parallel 3-stage exclusive scan ---------------
__global__ __launch_bounds__(1024) void kS1_tile_scan(int N)
{
    __shared__ int sh[1024];
    int t = threadIdx.x;
    int gi = blockIdx.x * 1024 + t;
    int v = (gi < N) ? d_deg[gi] : 0;
    sh[t] = v;
    __syncthreads();
#pragma unroll
    for (int off = 1; off < 1024; off <<= 1) {
        int u = (t >= off) ? sh[t - off] : 0;
        __syncthreads();
        sh[t] += u;
        __syncthreads();
    }
    if (gi < N) d_excl[gi] = sh[t] - v;
    if (t == 1023) d_bsum[blockIdx.x] = sh[t];
}

__global__ __launch_bounds__(128) void kS2_block_scan(int nTiles)
{
    __shared__ int sh[128];
    int t = threadIdx.x;
    int v = (t < nTiles) ? d_bsum[t] : 0;
    sh[t] = v;
    __syncthreads();
#pragma unroll
    for (int off = 1; off < 128; off <<= 1) {
        int u = (t >= off) ? sh[t - off] : 0;
        __syncthreads();
        sh[t] += u;
        __syncthreads();
    }
    if (t < nTiles) d_boff[t] = sh[t] - v;
}

__global__ __launch_bounds__(256) void kS3_finalize(int N, int E)
{
    int i = blockIdx.x * blockDim.x + threadIdx.x;
    if (i < N) {
        int s = d_excl[i] + d_boff[i >> 10];
        d_start[i]  = s;
        d_cursor[i] = s;
    }
    if (i == 0) d_start[N] = E;
}

// ---------------- K2c: decode + weight + place (single 8B record store) ------
__global__ __launch_bounds__(256) void k2c_place(
    const void* __restrict__ ei_raw, int E, int N)
{
    int i = blockIdx.x * blockDim.x + threadIdx.x;
    if (i >= E) return;
    int s, d;
    if (d_is64) {
        const long long* p = (const long long*)ei_raw;
        s = (int)p[i];
        d = (int)p[(size_t)E + i];
    } else {
        const int* p = (const int*)ei_raw;
        s = p[i];
        d = p[(size_t)E + i];
    }
    if ((unsigned)s >= (unsigned)N) s = 0;
    if ((unsigned)d >= (unsigned)N) d = 0;

    float w = __expf(lrelu(d_as[s] + d_ad[d]));
    int p = atomicAdd(&d_cursor[d], 1);
    d_rec[p] = make_int2(s, __float_as_int(w));
}

// ---------------- K5: per-node gather-aggregate (one warp per node) ----------
// Records loaded by all lanes directly (L1 broadcast); 4-way manual unroll
// keeps 4 independent 256B h-gathers in flight (MLP 4, no shfl serialization).
__global__ __launch_bounds__(256) void k5_gather(
    float2* __restrict__ out, const float* __restrict__ bias, int N)
{
    int t = threadIdx.x;
    int warp = t >> 5, lane = t & 31;
    int n = blockIdx.x * 8 + warp;
    if (n >= N) return;

    const float2* h2 = reinterpret_cast<const float2*>(d_h);

    float wself = __expf(lrelu(d_as[n] + d_ad[n]));
    float2 hv = h2[(size_t)n * 32 + lane];
    float accx = wself * hv.x;
    float accy = wself * hv.y;
    float wsum = wself;

    int beg = d_start[n], end = d_start[n + 1];
    int j = beg;
    for (; j + 4 <= end; j += 4) {
        int2 r0 = d_rec[j + 0];
        int2 r1 = d_rec[j + 1];
        int2 r2 = d_rec[j + 2];
        int2 r3 = d_rec[j + 3];
        float2 v0 = h2[(size_t)r0.x * 32 + lane];
        float2 v1 = h2[(size_t)r1.x * 32 + lane];
        float2 v2 = h2[(size_t)r2.x * 32 + lane];
        float2 v3 = h2[(size_t)r3.x * 32 + lane];
        float w0 = __int_as_float(r0.y);
        float w1 = __int_as_float(r1.y);
        float w2 = __int_as_float(r2.y);
        float w3 = __int_as_float(r3.y);
        accx = fmaf(w0, v0.x, accx); accy = fmaf(w0, v0.y, accy);
        accx = fmaf(w1, v1.x, accx); accy = fmaf(w1, v1.y, accy);
        accx = fmaf(w2, v2.x, accx); accy = fmaf(w2, v2.y, accy);
        accx = fmaf(w3, v3.x, accx); accy = fmaf(w3, v3.y, accy);
        wsum += w0 + w1 + w2 + w3;
    }
    for (; j < end; j++) {
        int2 r = d_rec[j];
        float w = __int_as_float(r.y);
        float2 v = h2[(size_t)r.x * 32 + lane];
        accx = fmaf(w, v.x, accx);
        accy = fmaf(w, v.y, accy);
        wsum += w;
    }

    float inv = 1.f / wsum;
    float2 b = reinterpret_cast<const float2*>(bias)[lane];
    out[(size_t)n * 32 + lane] = make_float2(accx * inv + b.x, accy * inv + b.y);
}

// ---------------- launch ------------------------------------------------------
extern "C" void kernel_launch(void* const* d_in, const int* in_sizes, int n_in,
                              void* d_out, int out_size)
{
    const float* x    = (const float*)d_in[0];
    const void*  ei   = d_in[1];
    const float* W    = (const float*)d_in[2];
    const float* asrc = (const float*)d_in[3];
    const float* adst = (const float*)d_in[4];
    const float* bias = (const float*)d_in[5];
    float*       out  = (float*)d_out;

    int N = in_sizes[0] / IN_DIM;
    int E = in_sizes[1] / 2;
    int nTiles = (N + 1023) / 1024;    // <= 128 for N <= 100k

    k0_detect<<<1, 1>>>((const long long*)ei, N);
    k1_gemm<<<(N + 31) / 32, 256>>>(x, W, asrc, adst, N);
    k2a_hist<<<(E + 255) / 256, 256>>>(ei, E, N);
    kS1_tile_scan<<<nTiles, 1024>>>(N);
    kS2_block_scan<<<1, 128>>>(nTiles);
    kS3_finalize<<<(N + 255) / 256, 256>>>(N, E);
    k2c_place<<<(E + 255) / 256, 256>>>(ei, E, N);
    k5_gather<<<(N + 7) / 8, 256>>>((float2*)out, bias, N);
}